// round 4
// baseline (speedup 1.0000x reference)
#include <cuda_runtime.h>
#include <cuda_bf16.h>
#include <math.h>
#include <stdint.h>

#define B_ROWS 4096
#define D_DIM  5000
#define H_DIM  512
#define Z_DIM  64
#define TOPK_K 50

typedef __nv_bfloat16  bf16;
typedef __nv_bfloat162 bf162;

// ======================= scratch (static device globals) =====================
__device__ bf16 g_xhi [B_ROWS*D_DIM],     g_xlo [B_ROWS*D_DIM];
__device__ bf16 g_w1hi[D_DIM*H_DIM],      g_w1lo[D_DIM*H_DIM];
__device__ bf16 g_w2hi[H_DIM*D_DIM],      g_w2lo[H_DIM*D_DIM];
__device__ bf16 g_ew1hi[D_DIM*2*H_DIM],   g_ew1lo[D_DIM*2*H_DIM];
__device__ bf16 g_ew2hi[2*H_DIM*H_DIM],   g_ew2lo[2*H_DIM*H_DIM];
__device__ bf16 g_ew3hi[H_DIM*H_DIM],     g_ew3lo[H_DIM*H_DIM];
__device__ bf16 g_ew4hi[H_DIM*H_DIM],     g_ew4lo[H_DIM*H_DIM];
__device__ bf16 g_mwhi[H_DIM*Z_DIM],      g_mwlo[H_DIM*Z_DIM];
__device__ bf16 g_lwhi[H_DIM*Z_DIM],      g_lwlo[H_DIM*Z_DIM];
__device__ bf16 g_dw1hi[Z_DIM*2*H_DIM],   g_dw1lo[Z_DIM*2*H_DIM];
__device__ bf16 g_dw2hi[2*H_DIM*D_DIM],   g_dw2lo[2*H_DIM*D_DIM];
__device__ float g_hf  [B_ROWS*H_DIM];
__device__ bf16  g_hhi [B_ROWS*H_DIM],    g_hlo [B_ROWS*H_DIM];
__device__ float g_wlog[B_ROWS*D_DIM];
__device__ bf16  g_xmhi[B_ROWS*D_DIM],    g_xmlo[B_ROWS*D_DIM];
__device__ bf16  g_e1hi[B_ROWS*2*H_DIM],  g_e1lo[B_ROWS*2*H_DIM];
__device__ bf16  g_e2hi[B_ROWS*H_DIM],    g_e2lo[B_ROWS*H_DIM];
__device__ bf16  g_e3hi[B_ROWS*H_DIM],    g_e3lo[B_ROWS*H_DIM];
__device__ bf16  g_e4hi[B_ROWS*H_DIM],    g_e4lo[B_ROWS*H_DIM];
__device__ bf16  g_zhi [B_ROWS*Z_DIM],    g_zlo [B_ROWS*Z_DIM];
__device__ bf16  g_dhi [B_ROWS*2*H_DIM],  g_dlo [B_ROWS*2*H_DIM];
__device__ float g_mean[H_DIM], g_rvar[H_DIM];

// ======================= PTX helpers ========================================
__device__ __forceinline__ void cp16(uint32_t dst, const void* src, uint32_t sz) {
    asm volatile("cp.async.cg.shared.global [%0], [%1], 16, %2;"
                 :: "r"(dst), "l"(src), "r"(sz));
}
__device__ __forceinline__ void cp_commit() {
    asm volatile("cp.async.commit_group;" ::: "memory");
}
__device__ __forceinline__ void cp_wait1() {
    asm volatile("cp.async.wait_group 1;" ::: "memory");
}
__device__ __forceinline__ void ldsm4(uint32_t* r, uint32_t a) {
    asm volatile("ldmatrix.sync.aligned.m8n8.x4.shared.b16 {%0,%1,%2,%3}, [%4];"
                 : "=r"(r[0]), "=r"(r[1]), "=r"(r[2]), "=r"(r[3]) : "r"(a));
}
__device__ __forceinline__ void ldsm4t(uint32_t* r, uint32_t a) {
    asm volatile("ldmatrix.sync.aligned.m8n8.x4.trans.shared.b16 {%0,%1,%2,%3}, [%4];"
                 : "=r"(r[0]), "=r"(r[1]), "=r"(r[2]), "=r"(r[3]) : "r"(a));
}
__device__ __forceinline__ void mma_bf16(float* c, const uint32_t* a, const uint32_t* b) {
    asm volatile("mma.sync.aligned.m16n8k16.row.col.f32.bf16.bf16.f32 "
                 "{%0,%1,%2,%3}, {%4,%5,%6,%7}, {%8,%9}, {%0,%1,%2,%3};"
                 : "+f"(c[0]), "+f"(c[1]), "+f"(c[2]), "+f"(c[3])
                 : "r"(a[0]), "r"(a[1]), "r"(a[2]), "r"(a[3]), "r"(b[0]), "r"(b[1]));
}
__device__ __forceinline__ void split2(float v, bf16& h, bf16& l) {
    h = __float2bfloat16(v);
    l = __float2bfloat16(v - __bfloat162float(h));
}

#define EPI_F32     0
#define EPI_LEAKY   1
#define EPI_GUMBEL  2
#define EPI_SIGMOID 3

// ======================= bf16-split tensor-core GEMM ========================
template<int BM, int BN, int WARPS_M, int WARPS_N, int EPI>
__global__ __launch_bounds__(256) void gemm_bs(
    const bf16* __restrict__ Ahi, const bf16* __restrict__ Alo,
    const bf16* __restrict__ Bhi, const bf16* __restrict__ Blo,
    const float* __restrict__ bias, const float* __restrict__ extra,
    float* __restrict__ Cf, bf16* __restrict__ Chi, bf16* __restrict__ Clo,
    int M, int N, int K)
{
    static_assert(WARPS_M * WARPS_N == 8, "");
    constexpr int BK   = 32;
    constexpr int AST  = BK + 8;
    constexpr int BNp  = BN + 8;
    constexpr int WTM  = BM / WARPS_M;
    constexpr int WTN  = BN / WARPS_N;
    constexpr int MT   = WTM / 16;
    constexpr int NT   = WTN / 8;
    constexpr int NL   = WTN / 16;
    constexpr int ASTG = BM * AST;
    constexpr int BSTG = BK * BNp;
    constexpr int A_PASS = BM / 64;
    constexpr int B_PASS = BN / 64;

    extern __shared__ bf16 sm[];
    const uint32_t smbase = (uint32_t)__cvta_generic_to_shared(sm);
    const uint32_t offAlo = 3 * ASTG, offBhi = 6 * ASTG, offBlo = 6 * ASTG + 3 * BSTG;

    const int tid  = threadIdx.x;
    const int lane = tid & 31, wid = tid >> 5;
    const int warp_m = wid % WARPS_M, warp_n = wid / WARPS_M;
    const int row0 = blockIdx.y * BM;
    const int col0 = blockIdx.x * BN;
    const int n_iters = (K + BK - 1) / BK;

    auto load_stage = [&](int s) {
        const int buf = s % 3;
        const int k0  = s * BK;
#pragma unroll
        for (int p = 0; p < A_PASS; p++) {
            int vec = tid + p * 256;
            int r = vec >> 2, q = vec & 3;
            size_t so = (size_t)(row0 + r) * K + k0 + q * 8;
            uint32_t ok = (k0 + q * 8 < K) ? 16u : 0u;
            const void* sh = ok ? (const void*)(Ahi + so) : (const void*)Ahi;
            const void* sl = ok ? (const void*)(Alo + so) : (const void*)Alo;
            uint32_t d = (uint32_t)((buf * ASTG + r * AST + q * 8) * 2);
            cp16(smbase + d, sh, ok);
            cp16(smbase + offAlo * 2 + d, sl, ok);
        }
#pragma unroll
        for (int p = 0; p < B_PASS; p++) {
            int vec = tid + p * 256;
            int kr = vec / (BN / 8), q = vec % (BN / 8);
            size_t so = (size_t)(k0 + kr) * N + col0 + q * 8;
            uint32_t ok = ((k0 + kr < K) && (col0 + q * 8 < N)) ? 16u : 0u;
            const void* sh = ok ? (const void*)(Bhi + so) : (const void*)Bhi;
            const void* sl = ok ? (const void*)(Blo + so) : (const void*)Blo;
            uint32_t d = (uint32_t)((buf * BSTG + kr * BNp + q * 8) * 2);
            cp16(smbase + offBhi * 2 + d, sh, ok);
            cp16(smbase + offBlo * 2 + d, sl, ok);
        }
    };

    load_stage(0); cp_commit();
    if (1 < n_iters) load_stage(1);
    cp_commit();

    float acc[MT][NT][4];
#pragma unroll
    for (int i = 0; i < MT; i++)
#pragma unroll
        for (int j = 0; j < NT; j++)
#pragma unroll
            for (int q = 0; q < 4; q++) acc[i][j][q] = 0.f;

    const int lrow  = lane & 15;
    const int lhalf = (lane >> 4) << 3;

    for (int it = 0; it < n_iters; it++) {
        cp_wait1();
        __syncthreads();
        const int buf = it % 3;

#pragma unroll
        for (int kk = 0; kk < BK; kk += 16) {
            uint32_t afh[MT][4], afl[MT][4], bfh[NT][2], bfl[NT][2];
#pragma unroll
            for (int i = 0; i < MT; i++) {
                int r = warp_m * WTM + i * 16 + lrow;
                uint32_t a = smbase + (uint32_t)((buf * ASTG + r * AST + kk + lhalf) * 2);
                ldsm4(afh[i], a);
                ldsm4(afl[i], a + offAlo * 2);
            }
#pragma unroll
            for (int j = 0; j < NL; j++) {
                int kr = kk + (lane & 15);
                int cc = warp_n * WTN + j * 16 + lhalf;
                uint32_t a = smbase + offBhi * 2
                           + (uint32_t)((buf * BSTG + kr * BNp + cc) * 2);
                ldsm4t(&bfh[2 * j][0], a);
                ldsm4t(&bfl[2 * j][0], a + (offBlo - offBhi) * 2);
            }
#pragma unroll
            for (int i = 0; i < MT; i++)
#pragma unroll
                for (int j = 0; j < NT; j++) mma_bf16(acc[i][j], afh[i], bfh[j]);
#pragma unroll
            for (int i = 0; i < MT; i++)
#pragma unroll
                for (int j = 0; j < NT; j++) mma_bf16(acc[i][j], afh[i], bfl[j]);
#pragma unroll
            for (int i = 0; i < MT; i++)
#pragma unroll
                for (int j = 0; j < NT; j++) mma_bf16(acc[i][j], afl[i], bfh[j]);
        }

        int s = it + 2;
        if (s < n_iters) load_stage(s);
        cp_commit();
        __syncthreads();
    }

#pragma unroll
    for (int i = 0; i < MT; i++) {
#pragma unroll
        for (int j = 0; j < NT; j++) {
            int row = row0 + warp_m * WTM + i * 16 + (lane >> 2);
            int col = col0 + warp_n * WTN + j * 8 + (lane & 3) * 2;
            if (col >= N) continue;
            float b0 = bias[col], b1 = bias[col + 1];
#pragma unroll
            for (int h = 0; h < 2; h++) {
                int r = row + h * 8;
                float v0 = acc[i][j][2 * h + 0] + b0;
                float v1 = acc[i][j][2 * h + 1] + b1;
                size_t off = (size_t)r * N + col;
                if (EPI == EPI_F32) {
                    *reinterpret_cast<float2*>(&Cf[off]) = make_float2(v0, v1);
                } else if (EPI == EPI_LEAKY) {
                    v0 = (v0 > 0.f) ? v0 : 0.01f * v0;
                    v1 = (v1 > 0.f) ? v1 : 0.01f * v1;
                    bf16 h0, l0, h1, l1;
                    split2(v0, h0, l0); split2(v1, h1, l1);
                    *reinterpret_cast<bf162*>(&Chi[off]) = __halves2bfloat162(h0, h1);
                    *reinterpret_cast<bf162*>(&Clo[off]) = __halves2bfloat162(l0, l1);
                } else if (EPI == EPI_GUMBEL) {
                    float2 u = *reinterpret_cast<const float2*>(&extra[off]);
                    v0 += __logf(-__logf(u.x + 1e-30f));
                    v1 += __logf(-__logf(u.y + 1e-30f));
                    *reinterpret_cast<float2*>(&Cf[off]) = make_float2(v0, v1);
                } else {
                    v0 = 1.0f / (1.0f + __expf(-v0));
                    v1 = 1.0f / (1.0f + __expf(-v1));
                    *reinterpret_cast<float2*>(&Cf[off]) = make_float2(v0, v1);
                }
            }
        }
    }
}

// ======================= elementwise kernels ================================
__global__ __launch_bounds__(256) void convert_split_k(
    const float4* __restrict__ in, bf162* __restrict__ hi, bf162* __restrict__ lo, int n4)
{
    int i = blockIdx.x * 256 + threadIdx.x;
    if (i >= n4) return;
    float4 v = in[i];
    bf16 h0, l0, h1, l1, h2, l2, h3, l3;
    split2(v.x, h0, l0); split2(v.y, h1, l1);
    split2(v.z, h2, l2); split2(v.w, h3, l3);
    hi[2 * i]     = __halves2bfloat162(h0, h1);
    hi[2 * i + 1] = __halves2bfloat162(h2, h3);
    lo[2 * i]     = __halves2bfloat162(l0, l1);
    lo[2 * i + 1] = __halves2bfloat162(l2, l3);
}

__global__ __launch_bounds__(256) void bn_stats(
    const float* __restrict__ h, float* __restrict__ mean, float* __restrict__ rvar,
    int M, int N)
{
    const int c = blockIdx.x;
    float s = 0.f, s2 = 0.f;
    for (int r = threadIdx.x; r < M; r += 256) {
        float v = h[(size_t)r * N + c];
        s += v; s2 += v * v;
    }
    __shared__ float sh[256], sh2[256];
    sh[threadIdx.x] = s; sh2[threadIdx.x] = s2;
    __syncthreads();
    for (int o = 128; o > 0; o >>= 1) {
        if (threadIdx.x < o) {
            sh[threadIdx.x]  += sh[threadIdx.x + o];
            sh2[threadIdx.x] += sh2[threadIdx.x + o];
        }
        __syncthreads();
    }
    if (threadIdx.x == 0) {
        float m = sh[0] / (float)M;
        float var = sh2[0] / (float)M - m * m;
        mean[c] = m;
        rvar[c] = rsqrtf(var + 1e-5f);
    }
}

__global__ __launch_bounds__(256) void bn_apply_relu_conv(
    const float* __restrict__ h, const float* __restrict__ mean,
    const float* __restrict__ rvar, const float* __restrict__ g,
    const float* __restrict__ b, bf16* __restrict__ hi, bf16* __restrict__ lo,
    int total, int N)
{
    int i = blockIdx.x * 256 + threadIdx.x;
    if (i >= total) return;
    int c = i % N;
    float v = (h[i] - mean[c]) * rvar[c] * g[c] + b[c];
    v = v > 0.f ? v : 0.f;
    bf16 hh, ll; split2(v, hh, ll);
    hi[i] = hh; lo[i] = ll;
}

__global__ __launch_bounds__(256) void reparam_conv(
    const float* __restrict__ mu, const float* __restrict__ logvar,
    const float* __restrict__ eps, bf16* __restrict__ zhi, bf16* __restrict__ zlo,
    int total)
{
    int i = blockIdx.x * 256 + threadIdx.x;
    if (i >= total) return;
    float z = mu[i] + eps[i] * __expf(0.5f * logvar[i]);
    bf16 h, l; split2(z, h, l);
    zhi[i] = h; zlo[i] = l;
}

// ======================= continuous top-k (register-resident) ===============
// ws kept scaled: ws' = w * 10 * log2(e). Then:
//   softmax prob p_i = exp2(ws'_i - gm') / sum
//   suppression   w += log(mask)  <=>  ws' += 10*log2(mask)
// Warp-uniform fast paths decided from (warp_max' - global_max'):
//   < -125.5 : all exp2 underflow -> whole body skipped (matches fp32 ref)
//   < -14.0  : all p < 6e-5 -> log(1-p) ~= -(p + p^2/2)  (error < 1e-13)
#define TK_NT  256
#define TK_PER 20
#define LOG2E10 14.426950408889634f

__device__ __forceinline__ float warpSum(float v) {
#pragma unroll
    for (int o = 16; o; o >>= 1) v += __shfl_xor_sync(0xffffffffu, v, o);
    return v;
}
__device__ __forceinline__ float warpMax(float v) {
#pragma unroll
    for (int o = 16; o; o >>= 1) v = fmaxf(v, __shfl_xor_sync(0xffffffffu, v, o));
    return v;
}

__global__ __launch_bounds__(TK_NT) void topk_mask_kernel(
    const float* __restrict__ W, const float* __restrict__ X,
    bf16* __restrict__ XMhi, bf16* __restrict__ XMlo)
{
    __shared__ float sred0[TK_NT / 32];
    __shared__ float sred1[TK_NT / 32];

    const int row = blockIdx.x;
    const int tid = threadIdx.x;
    const int lane = tid & 31;
    const int wid = tid >> 5;
    const float* wr = W + (size_t)row * D_DIM;

    float ws[TK_PER], kh[TK_PER];
#pragma unroll
    for (int j = 0; j < TK_PER; j++) {
        int i = tid + j * TK_NT;
        ws[j] = (i < D_DIM) ? wr[i] * LOG2E10 : -INFINITY;
        kh[j] = 0.f;
    }

    for (int it = 0; it < TOPK_K; it++) {
        // ---- global max (scaled) ----
        float m = ws[0];
#pragma unroll
        for (int j = 1; j < TK_PER; j++) m = fmaxf(m, ws[j]);
        float wm = warpMax(m);
        if (lane == 0) sred0[wid] = wm;
        __syncthreads();
        float gm = sred0[0];
#pragma unroll
        for (int w = 1; w < TK_NT / 32; w++) gm = fmaxf(gm, sred0[w]);

        const float d = wm - gm;          // warp-uniform
        const bool live = d > -125.5f;    // else all exp2 underflow to 0

        // ---- exp2 + sum ----
        float e[TK_PER];
        float s = 0.f;
        if (live) {
#pragma unroll
            for (int j = 0; j < TK_PER; j++) {
                e[j] = exp2f(ws[j] - gm);
                s += e[j];
            }
        }
        float wsum = warpSum(live ? s : 0.f);
        if (lane == 0) sred1[wid] = wsum;
        __syncthreads();
        float S = sred1[0];
#pragma unroll
        for (int w = 1; w < TK_NT / 32; w++) S += sred1[w];
        const float rs = 1.0f / S;        // S >= 1 always

        // ---- accumulate khot, suppress ----
        if (live) {
            if (d < -14.0f) {
                // all p < 6e-5: series for log(1-p)
#pragma unroll
                for (int j = 0; j < TK_PER; j++) {
                    float p = e[j] * rs;
                    kh[j] += p;
                    float t = p + 0.5f * p * p;       // -ln(1-p) approx
                    ws[j] = fmaf(t, -LOG2E10, ws[j]);
                }
            } else {
#pragma unroll
                for (int j = 0; j < TK_PER; j++) {
                    float p = e[j] * rs;
                    kh[j] += p;
                    float mask = fmaxf(1.0f - p, 1e-30f);
                    ws[j] = fmaf(__log2f(mask), 10.0f, ws[j]);
                }
            }
        }
        __syncthreads();   // protect sred0 for next iteration
    }

    const float* xr = X + (size_t)row * D_DIM;
    bf16* xh = XMhi + (size_t)row * D_DIM;
    bf16* xl = XMlo + (size_t)row * D_DIM;
#pragma unroll
    for (int j = 0; j < TK_PER; j++) {
        int i = tid + j * TK_NT;
        if (i < D_DIM) {
            float v = xr[i] * kh[j];
            bf16 h, l; split2(v, h, l);
            xh[i] = h; xl[i] = l;
        }
    }
}

// ======================= host side ==========================================
#define SYM(p, s) cudaGetSymbolAddress((void**)&p, s)

template<int BM, int BN, int WM, int WN, int EPI>
static inline void launch_gemm(
    const bf16* Ahi, const bf16* Alo, const bf16* Bhi, const bf16* Blo,
    const float* bias, const float* extra,
    float* Cf, bf16* Chi, bf16* Clo, int M, int N, int K)
{
    constexpr int ASTG = BM * 40, BSTG = 32 * (BN + 8);
    constexpr int smem = (6 * ASTG + 6 * BSTG) * 2;
    cudaFuncSetAttribute(gemm_bs<BM, BN, WM, WN, EPI>,
                         cudaFuncAttributeMaxDynamicSharedMemorySize, smem);
    dim3 g((N + BN - 1) / BN, M / BM);
    gemm_bs<BM, BN, WM, WN, EPI><<<g, 256, smem>>>(
        Ahi, Alo, Bhi, Blo, bias, extra, Cf, Chi, Clo, M, N, K);
}

static inline void conv(const float* in, bf16* hi, bf16* lo, int n)
{
    int n4 = n / 4;
    convert_split_k<<<(n4 + 255) / 256, 256>>>(
        (const float4*)in, (bf162*)hi, (bf162*)lo, n4);
}

extern "C" void kernel_launch(void* const* d_in, const int* in_sizes, int n_in,
                              void* d_out, int out_size)
{
    const float* x        = (const float*)d_in[0];
    const float* noise_u  = (const float*)d_in[1];
    const float* eps      = (const float*)d_in[2];
    const float* wc_w1    = (const float*)d_in[3];
    const float* wc_b1    = (const float*)d_in[4];
    const float* bn_g     = (const float*)d_in[5];
    const float* bn_b     = (const float*)d_in[6];
    const float* wc_w2    = (const float*)d_in[7];
    const float* wc_b2    = (const float*)d_in[8];
    const float* enc_w1   = (const float*)d_in[9];
    const float* enc_b1   = (const float*)d_in[10];
    const float* enc_w2   = (const float*)d_in[11];
    const float* enc_b2   = (const float*)d_in[12];
    const float* enc_w3   = (const float*)d_in[13];
    const float* enc_b3   = (const float*)d_in[14];
    const float* enc_w4   = (const float*)d_in[15];
    const float* enc_b4   = (const float*)d_in[16];
    const float* mean_w   = (const float*)d_in[17];
    const float* mean_b   = (const float*)d_in[18];
    const float* logvar_w = (const float*)d_in[19];
    const float* logvar_b = (const float*)d_in[20];
    const float* dec_w1   = (const float*)d_in[21];
    const float* dec_b1   = (const float*)d_in[22];
    const float* dec_w2   = (const float*)d_in[23];
    const float* dec_b2   = (const float*)d_in[24];

    float* out    = (float*)d_out;
    float* mu_x   = out;
    float* mu_lat = out + (size_t)B_ROWS * D_DIM;
    float* logvar = mu_lat + (size_t)B_ROWS * Z_DIM;

    bf16 *xhi,*xlo,*w1hi,*w1lo,*w2hi,*w2lo,*ew1hi,*ew1lo,*ew2hi,*ew2lo,
         *ew3hi,*ew3lo,*ew4hi,*ew4lo,*mwhi,*mwlo,*lwhi,*lwlo,
         *dw1hi,*dw1lo,*dw2hi,*dw2lo,
         *hhi,*hlo,*xmhi,*xmlo,*e1hi,*e1lo,*e2hi,*e2lo,*e3hi,*e3lo,
         *e4hi,*e4lo,*zhi,*zlo,*dhi,*dlo;
    float *hf,*wlog,*mean,*rvar;
    SYM(xhi,g_xhi);   SYM(xlo,g_xlo);
    SYM(w1hi,g_w1hi); SYM(w1lo,g_w1lo); SYM(w2hi,g_w2hi); SYM(w2lo,g_w2lo);
    SYM(ew1hi,g_ew1hi); SYM(ew1lo,g_ew1lo); SYM(ew2hi,g_ew2hi); SYM(ew2lo,g_ew2lo);
    SYM(ew3hi,g_ew3hi); SYM(ew3lo,g_ew3lo); SYM(ew4hi,g_ew4hi); SYM(ew4lo,g_ew4lo);
    SYM(mwhi,g_mwhi); SYM(mwlo,g_mwlo); SYM(lwhi,g_lwhi); SYM(lwlo,g_lwlo);
    SYM(dw1hi,g_dw1hi); SYM(dw1lo,g_dw1lo); SYM(dw2hi,g_dw2hi); SYM(dw2lo,g_dw2lo);
    SYM(hf,g_hf); SYM(hhi,g_hhi); SYM(hlo,g_hlo); SYM(wlog,g_wlog);
    SYM(xmhi,g_xmhi); SYM(xmlo,g_xmlo);
    SYM(e1hi,g_e1hi); SYM(e1lo,g_e1lo); SYM(e2hi,g_e2hi); SYM(e2lo,g_e2lo);
    SYM(e3hi,g_e3hi); SYM(e3lo,g_e3lo); SYM(e4hi,g_e4hi); SYM(e4lo,g_e4lo);
    SYM(zhi,g_zhi); SYM(zlo,g_zlo); SYM(dhi,g_dhi); SYM(dlo,g_dlo);
    SYM(mean,g_mean); SYM(rvar,g_rvar);

    // ---- input/weight splits ----
    conv(x,        xhi,  xlo,  B_ROWS * D_DIM);
    conv(wc_w1,    w1hi, w1lo, D_DIM * H_DIM);
    conv(wc_w2,    w2hi, w2lo, H_DIM * D_DIM);
    conv(enc_w1,   ew1hi, ew1lo, D_DIM * 2 * H_DIM);
    conv(enc_w2,   ew2hi, ew2lo, 2 * H_DIM * H_DIM);
    conv(enc_w3,   ew3hi, ew3lo, H_DIM * H_DIM);
    conv(enc_w4,   ew4hi, ew4lo, H_DIM * H_DIM);
    conv(mean_w,   mwhi, mwlo, H_DIM * Z_DIM);
    conv(logvar_w, lwhi, lwlo, H_DIM * Z_DIM);
    conv(dec_w1,   dw1hi, dw1lo, Z_DIM * 2 * H_DIM);
    conv(dec_w2,   dw2hi, dw2lo, 2 * H_DIM * D_DIM);

    // ---- weight_creator ----
    launch_gemm<128, 128, 2, 4, EPI_F32>(xhi, xlo, w1hi, w1lo, wc_b1, nullptr,
                                         hf, nullptr, nullptr, B_ROWS, H_DIM, D_DIM);
    bn_stats<<<H_DIM, 256>>>(hf, mean, rvar, B_ROWS, H_DIM);
    bn_apply_relu_conv<<<(B_ROWS * H_DIM + 255) / 256, 256>>>(
        hf, mean, rvar, bn_g, bn_b, hhi, hlo, B_ROWS * H_DIM, H_DIM);
    launch_gemm<128, 128, 2, 4, EPI_GUMBEL>(hhi, hlo, w2hi, w2lo, wc_b2, noise_u,
                                            wlog, nullptr, nullptr, B_ROWS, D_DIM, H_DIM);

    // ---- differentiable top-k + mask ----
    topk_mask_kernel<<<B_ROWS, TK_NT>>>(wlog, x, xmhi, xmlo);

    // ---- encoder ----
    launch_gemm<128, 128, 2, 4, EPI_LEAKY>(xmhi, xmlo, ew1hi, ew1lo, enc_b1, nullptr,
                                           nullptr, e1hi, e1lo, B_ROWS, 2 * H_DIM, D_DIM);
    launch_gemm<128, 128, 2, 4, EPI_LEAKY>(e1hi, e1lo, ew2hi, ew2lo, enc_b2, nullptr,
                                           nullptr, e2hi, e2lo, B_ROWS, H_DIM, 2 * H_DIM);
    launch_gemm<128, 128, 2, 4, EPI_LEAKY>(e2hi, e2lo, ew3hi, ew3lo, enc_b3, nullptr,
                                           nullptr, e3hi, e3lo, B_ROWS, H_DIM, H_DIM);
    launch_gemm<128, 128, 2, 4, EPI_LEAKY>(e3hi, e3lo, ew4hi, ew4lo, enc_b4, nullptr,
                                           nullptr, e4hi, e4lo, B_ROWS, H_DIM, H_DIM);
    launch_gemm<64, 64, 2, 4, EPI_F32>(e4hi, e4lo, mwhi, mwlo, mean_b, nullptr,
                                       mu_lat, nullptr, nullptr, B_ROWS, Z_DIM, H_DIM);
    launch_gemm<64, 64, 2, 4, EPI_F32>(e4hi, e4lo, lwhi, lwlo, logvar_b, nullptr,
                                       logvar, nullptr, nullptr, B_ROWS, Z_DIM, H_DIM);

    // ---- reparameterize ----
    reparam_conv<<<(B_ROWS * Z_DIM + 255) / 256, 256>>>(
        mu_lat, logvar, eps, zhi, zlo, B_ROWS * Z_DIM);

    // ---- decoder ----
    launch_gemm<64, 64, 2, 4, EPI_LEAKY>(zhi, zlo, dw1hi, dw1lo, dec_b1, nullptr,
                                         nullptr, dhi, dlo, B_ROWS, 2 * H_DIM, Z_DIM);
    launch_gemm<128, 128, 2, 4, EPI_SIGMOID>(dhi, dlo, dw2hi, dw2lo, dec_b2, nullptr,
                                             mu_x, nullptr, nullptr, B_ROWS, D_DIM, 2 * H_DIM);
}

// round 5
// speedup vs baseline: 1.4055x; 1.4055x over previous
#include <cuda_runtime.h>
#include <cuda_bf16.h>
#include <math.h>
#include <stdint.h>

#define B_ROWS 4096
#define D_DIM  5000
#define H_DIM  512
#define Z_DIM  64
#define TOPK_K 50

typedef __nv_bfloat16  bf16;
typedef __nv_bfloat162 bf162;

// ======================= scratch (static device globals) =====================
__device__ bf16 g_xhi [B_ROWS*D_DIM],     g_xlo [B_ROWS*D_DIM];
__device__ bf16 g_w1hi[D_DIM*H_DIM],      g_w1lo[D_DIM*H_DIM];
__device__ bf16 g_w2hi[H_DIM*D_DIM],      g_w2lo[H_DIM*D_DIM];
__device__ bf16 g_ew1hi[D_DIM*2*H_DIM],   g_ew1lo[D_DIM*2*H_DIM];
__device__ bf16 g_ew2hi[2*H_DIM*H_DIM],   g_ew2lo[2*H_DIM*H_DIM];
__device__ bf16 g_ew3hi[H_DIM*H_DIM],     g_ew3lo[H_DIM*H_DIM];
__device__ bf16 g_ew4hi[H_DIM*H_DIM],     g_ew4lo[H_DIM*H_DIM];
__device__ bf16 g_mwhi[H_DIM*Z_DIM],      g_mwlo[H_DIM*Z_DIM];
__device__ bf16 g_lwhi[H_DIM*Z_DIM],      g_lwlo[H_DIM*Z_DIM];
__device__ bf16 g_dw1hi[Z_DIM*2*H_DIM],   g_dw1lo[Z_DIM*2*H_DIM];
__device__ bf16 g_dw2hi[2*H_DIM*D_DIM],   g_dw2lo[2*H_DIM*D_DIM];
__device__ float g_hf  [B_ROWS*H_DIM];
__device__ bf16  g_hhi [B_ROWS*H_DIM],    g_hlo [B_ROWS*H_DIM];
__device__ float g_wlog[B_ROWS*D_DIM];
__device__ bf16  g_xmhi[B_ROWS*D_DIM],    g_xmlo[B_ROWS*D_DIM];
__device__ bf16  g_e1hi[B_ROWS*2*H_DIM],  g_e1lo[B_ROWS*2*H_DIM];
__device__ bf16  g_e2hi[B_ROWS*H_DIM],    g_e2lo[B_ROWS*H_DIM];
__device__ bf16  g_e3hi[B_ROWS*H_DIM],    g_e3lo[B_ROWS*H_DIM];
__device__ bf16  g_e4hi[B_ROWS*H_DIM],    g_e4lo[B_ROWS*H_DIM];
__device__ bf16  g_zhi [B_ROWS*Z_DIM],    g_zlo [B_ROWS*Z_DIM];
__device__ bf16  g_dhi [B_ROWS*2*H_DIM],  g_dlo [B_ROWS*2*H_DIM];
__device__ float g_mean[H_DIM], g_rvar[H_DIM];

// ======================= PTX helpers ========================================
__device__ __forceinline__ void cp16(uint32_t dst, const void* src, uint32_t sz) {
    asm volatile("cp.async.cg.shared.global [%0], [%1], 16, %2;"
                 :: "r"(dst), "l"(src), "r"(sz));
}
__device__ __forceinline__ void cp_commit() {
    asm volatile("cp.async.commit_group;" ::: "memory");
}
__device__ __forceinline__ void cp_wait1() {
    asm volatile("cp.async.wait_group 1;" ::: "memory");
}
__device__ __forceinline__ void ldsm4(uint32_t* r, uint32_t a) {
    asm volatile("ldmatrix.sync.aligned.m8n8.x4.shared.b16 {%0,%1,%2,%3}, [%4];"
                 : "=r"(r[0]), "=r"(r[1]), "=r"(r[2]), "=r"(r[3]) : "r"(a));
}
__device__ __forceinline__ void ldsm4t(uint32_t* r, uint32_t a) {
    asm volatile("ldmatrix.sync.aligned.m8n8.x4.trans.shared.b16 {%0,%1,%2,%3}, [%4];"
                 : "=r"(r[0]), "=r"(r[1]), "=r"(r[2]), "=r"(r[3]) : "r"(a));
}
__device__ __forceinline__ void mma_bf16(float* c, const uint32_t* a, const uint32_t* b) {
    asm volatile("mma.sync.aligned.m16n8k16.row.col.f32.bf16.bf16.f32 "
                 "{%0,%1,%2,%3}, {%4,%5,%6,%7}, {%8,%9}, {%0,%1,%2,%3};"
                 : "+f"(c[0]), "+f"(c[1]), "+f"(c[2]), "+f"(c[3])
                 : "r"(a[0]), "r"(a[1]), "r"(a[2]), "r"(a[3]), "r"(b[0]), "r"(b[1]));
}
__device__ __forceinline__ void split2(float v, bf16& h, bf16& l) {
    h = __float2bfloat16(v);
    l = __float2bfloat16(v - __bfloat162float(h));
}

#define EPI_F32     0
#define EPI_LEAKY   1
#define EPI_GUMBEL  2
#define EPI_SIGMOID 3

// ======================= bf16-split tensor-core GEMM ========================
template<int BM, int BN, int WARPS_M, int WARPS_N, int EPI>
__global__ __launch_bounds__(256) void gemm_bs(
    const bf16* __restrict__ Ahi, const bf16* __restrict__ Alo,
    const bf16* __restrict__ Bhi, const bf16* __restrict__ Blo,
    const float* __restrict__ bias, const float* __restrict__ extra,
    float* __restrict__ Cf, bf16* __restrict__ Chi, bf16* __restrict__ Clo,
    int M, int N, int K)
{
    static_assert(WARPS_M * WARPS_N == 8, "");
    constexpr int BK   = 32;
    constexpr int AST  = BK + 8;
    constexpr int BNp  = BN + 8;
    constexpr int WTM  = BM / WARPS_M;
    constexpr int WTN  = BN / WARPS_N;
    constexpr int MT   = WTM / 16;
    constexpr int NT   = WTN / 8;
    constexpr int NL   = WTN / 16;
    constexpr int ASTG = BM * AST;
    constexpr int BSTG = BK * BNp;
    constexpr int A_PASS = BM / 64;
    constexpr int B_PASS = BN / 64;

    extern __shared__ bf16 sm[];
    const uint32_t smbase = (uint32_t)__cvta_generic_to_shared(sm);
    const uint32_t offAlo = 3 * ASTG, offBhi = 6 * ASTG, offBlo = 6 * ASTG + 3 * BSTG;

    const int tid  = threadIdx.x;
    const int lane = tid & 31, wid = tid >> 5;
    const int warp_m = wid % WARPS_M, warp_n = wid / WARPS_M;
    const int row0 = blockIdx.y * BM;
    const int col0 = blockIdx.x * BN;
    const int n_iters = (K + BK - 1) / BK;

    auto load_stage = [&](int s) {
        const int buf = s % 3;
        const int k0  = s * BK;
#pragma unroll
        for (int p = 0; p < A_PASS; p++) {
            int vec = tid + p * 256;
            int r = vec >> 2, q = vec & 3;
            size_t so = (size_t)(row0 + r) * K + k0 + q * 8;
            uint32_t ok = (k0 + q * 8 < K) ? 16u : 0u;
            const void* sh = ok ? (const void*)(Ahi + so) : (const void*)Ahi;
            const void* sl = ok ? (const void*)(Alo + so) : (const void*)Alo;
            uint32_t d = (uint32_t)((buf * ASTG + r * AST + q * 8) * 2);
            cp16(smbase + d, sh, ok);
            cp16(smbase + offAlo * 2 + d, sl, ok);
        }
#pragma unroll
        for (int p = 0; p < B_PASS; p++) {
            int vec = tid + p * 256;
            int kr = vec / (BN / 8), q = vec % (BN / 8);
            size_t so = (size_t)(k0 + kr) * N + col0 + q * 8;
            uint32_t ok = ((k0 + kr < K) && (col0 + q * 8 < N)) ? 16u : 0u;
            const void* sh = ok ? (const void*)(Bhi + so) : (const void*)Bhi;
            const void* sl = ok ? (const void*)(Blo + so) : (const void*)Blo;
            uint32_t d = (uint32_t)((buf * BSTG + kr * BNp + q * 8) * 2);
            cp16(smbase + offBhi * 2 + d, sh, ok);
            cp16(smbase + offBlo * 2 + d, sl, ok);
        }
    };

    load_stage(0); cp_commit();
    if (1 < n_iters) load_stage(1);
    cp_commit();

    float acc[MT][NT][4];
#pragma unroll
    for (int i = 0; i < MT; i++)
#pragma unroll
        for (int j = 0; j < NT; j++)
#pragma unroll
            for (int q = 0; q < 4; q++) acc[i][j][q] = 0.f;

    const int lrow  = lane & 15;
    const int lhalf = (lane >> 4) << 3;

    for (int it = 0; it < n_iters; it++) {
        cp_wait1();
        __syncthreads();
        const int buf = it % 3;

#pragma unroll
        for (int kk = 0; kk < BK; kk += 16) {
            uint32_t afh[MT][4], afl[MT][4], bfh[NT][2], bfl[NT][2];
#pragma unroll
            for (int i = 0; i < MT; i++) {
                int r = warp_m * WTM + i * 16 + lrow;
                uint32_t a = smbase + (uint32_t)((buf * ASTG + r * AST + kk + lhalf) * 2);
                ldsm4(afh[i], a);
                ldsm4(afl[i], a + offAlo * 2);
            }
#pragma unroll
            for (int j = 0; j < NL; j++) {
                int kr = kk + (lane & 15);
                int cc = warp_n * WTN + j * 16 + lhalf;
                uint32_t a = smbase + offBhi * 2
                           + (uint32_t)((buf * BSTG + kr * BNp + cc) * 2);
                ldsm4t(&bfh[2 * j][0], a);
                ldsm4t(&bfl[2 * j][0], a + (offBlo - offBhi) * 2);
            }
#pragma unroll
            for (int i = 0; i < MT; i++)
#pragma unroll
                for (int j = 0; j < NT; j++) mma_bf16(acc[i][j], afh[i], bfh[j]);
#pragma unroll
            for (int i = 0; i < MT; i++)
#pragma unroll
                for (int j = 0; j < NT; j++) mma_bf16(acc[i][j], afh[i], bfl[j]);
#pragma unroll
            for (int i = 0; i < MT; i++)
#pragma unroll
                for (int j = 0; j < NT; j++) mma_bf16(acc[i][j], afl[i], bfh[j]);
        }

        int s = it + 2;
        if (s < n_iters) load_stage(s);
        cp_commit();
        __syncthreads();
    }

#pragma unroll
    for (int i = 0; i < MT; i++) {
#pragma unroll
        for (int j = 0; j < NT; j++) {
            int row = row0 + warp_m * WTM + i * 16 + (lane >> 2);
            int col = col0 + warp_n * WTN + j * 8 + (lane & 3) * 2;
            if (col >= N) continue;
            float b0 = bias[col], b1 = bias[col + 1];
#pragma unroll
            for (int h = 0; h < 2; h++) {
                int r = row + h * 8;
                float v0 = acc[i][j][2 * h + 0] + b0;
                float v1 = acc[i][j][2 * h + 1] + b1;
                size_t off = (size_t)r * N + col;
                if (EPI == EPI_F32) {
                    *reinterpret_cast<float2*>(&Cf[off]) = make_float2(v0, v1);
                } else if (EPI == EPI_LEAKY) {
                    v0 = (v0 > 0.f) ? v0 : 0.01f * v0;
                    v1 = (v1 > 0.f) ? v1 : 0.01f * v1;
                    bf16 h0, l0, h1, l1;
                    split2(v0, h0, l0); split2(v1, h1, l1);
                    *reinterpret_cast<bf162*>(&Chi[off]) = __halves2bfloat162(h0, h1);
                    *reinterpret_cast<bf162*>(&Clo[off]) = __halves2bfloat162(l0, l1);
                } else if (EPI == EPI_GUMBEL) {
                    float2 u = *reinterpret_cast<const float2*>(&extra[off]);
                    v0 += __logf(-__logf(u.x + 1e-30f));
                    v1 += __logf(-__logf(u.y + 1e-30f));
                    *reinterpret_cast<float2*>(&Cf[off]) = make_float2(v0, v1);
                } else {
                    v0 = 1.0f / (1.0f + __expf(-v0));
                    v1 = 1.0f / (1.0f + __expf(-v1));
                    *reinterpret_cast<float2*>(&Cf[off]) = make_float2(v0, v1);
                }
            }
        }
    }
}

// ======================= fused segmented split-convert ======================
#define NSEG 11
struct ConvSeg { const float4* s; bf162* h; bf162* l; unsigned n4; };
struct ConvTable { ConvSeg seg[NSEG]; };

__global__ __launch_bounds__(256) void convert_all(ConvTable t, unsigned total)
{
    unsigned idx = blockIdx.x * 256 + threadIdx.x;
    if (idx >= total) return;
#pragma unroll
    for (int k = 0; k < NSEG; k++) {
        if (idx < t.seg[k].n4) {
            float4 v = t.seg[k].s[idx];
            bf16 h0, l0, h1, l1, h2, l2, h3, l3;
            split2(v.x, h0, l0); split2(v.y, h1, l1);
            split2(v.z, h2, l2); split2(v.w, h3, l3);
            t.seg[k].h[2 * idx]     = __halves2bfloat162(h0, h1);
            t.seg[k].h[2 * idx + 1] = __halves2bfloat162(h2, h3);
            t.seg[k].l[2 * idx]     = __halves2bfloat162(l0, l1);
            t.seg[k].l[2 * idx + 1] = __halves2bfloat162(l2, l3);
            return;
        }
        idx -= t.seg[k].n4;
    }
}

// ======================= BN / reparam =======================================
__global__ __launch_bounds__(256) void bn_stats(
    const float* __restrict__ h, float* __restrict__ mean, float* __restrict__ rvar,
    int M, int N)
{
    const int c = blockIdx.x;
    float s = 0.f, s2 = 0.f;
    for (int r = threadIdx.x; r < M; r += 256) {
        float v = h[(size_t)r * N + c];
        s += v; s2 += v * v;
    }
    __shared__ float sh[256], sh2[256];
    sh[threadIdx.x] = s; sh2[threadIdx.x] = s2;
    __syncthreads();
    for (int o = 128; o > 0; o >>= 1) {
        if (threadIdx.x < o) {
            sh[threadIdx.x]  += sh[threadIdx.x + o];
            sh2[threadIdx.x] += sh2[threadIdx.x + o];
        }
        __syncthreads();
    }
    if (threadIdx.x == 0) {
        float m = sh[0] / (float)M;
        float var = sh2[0] / (float)M - m * m;
        mean[c] = m;
        rvar[c] = rsqrtf(var + 1e-5f);
    }
}

__global__ __launch_bounds__(256) void bn_apply_relu_conv(
    const float* __restrict__ h, const float* __restrict__ mean,
    const float* __restrict__ rvar, const float* __restrict__ g,
    const float* __restrict__ b, bf16* __restrict__ hi, bf16* __restrict__ lo,
    int total, int N)
{
    int i = blockIdx.x * 256 + threadIdx.x;
    if (i >= total) return;
    int c = i % N;
    float v = (h[i] - mean[c]) * rvar[c] * g[c] + b[c];
    v = v > 0.f ? v : 0.f;
    bf16 hh, ll; split2(v, hh, ll);
    hi[i] = hh; lo[i] = ll;
}

__global__ __launch_bounds__(256) void reparam_conv(
    const float* __restrict__ mu, const float* __restrict__ logvar,
    const float* __restrict__ eps, bf16* __restrict__ zhi, bf16* __restrict__ zlo,
    int total)
{
    int i = blockIdx.x * 256 + threadIdx.x;
    if (i >= total) return;
    float z = mu[i] + eps[i] * __expf(0.5f * logvar[i]);
    bf16 h, l; split2(z, h, l);
    zhi[i] = h; zlo[i] = l;
}

// ======================= continuous top-k (register-resident) ===============
// ws scaled: ws' = w * 10 * log2(e).
//   p_i = exp2(ws'_i - gm') / S
//   suppression: ws' += 10*log2(max(1-p,1e-30))
// Per-ELEMENT fast path: p <= 6.1e-5 -> log(1-p) = -(p + p^2/2), err < p^3/3
// (< 1e-13, below fp32 ulp). Only elements near the current max (~1% of
// warp-instructions) take the MUFU log path.
#define TK_NT  256
#define TK_PER 20
#define LOG2E10 14.426950408889634f

__device__ __forceinline__ float warpSum(float v) {
#pragma unroll
    for (int o = 16; o; o >>= 1) v += __shfl_xor_sync(0xffffffffu, v, o);
    return v;
}
__device__ __forceinline__ float warpMax(float v) {
#pragma unroll
    for (int o = 16; o; o >>= 1) v = fmaxf(v, __shfl_xor_sync(0xffffffffu, v, o));
    return v;
}

__global__ __launch_bounds__(TK_NT) void topk_mask_kernel(
    const float* __restrict__ W, const float* __restrict__ X,
    bf16* __restrict__ XMhi, bf16* __restrict__ XMlo)
{
    __shared__ float sred0[TK_NT / 32];
    __shared__ float sred1[TK_NT / 32];

    const int row = blockIdx.x;
    const int tid = threadIdx.x;
    const int lane = tid & 31;
    const int wid = tid >> 5;
    const float* wr = W + (size_t)row * D_DIM;

    float ws[TK_PER], kh[TK_PER];
#pragma unroll
    for (int j = 0; j < TK_PER; j++) {
        int i = tid + j * TK_NT;
        ws[j] = (i < D_DIM) ? wr[i] * LOG2E10 : -INFINITY;
        kh[j] = 0.f;
    }

    for (int it = 0; it < TOPK_K; it++) {
        // ---- global max (scaled) ----
        float m = ws[0];
#pragma unroll
        for (int j = 1; j < TK_PER; j++) m = fmaxf(m, ws[j]);
        float wm = warpMax(m);
        if (lane == 0) sred0[wid] = wm;
        __syncthreads();
        float gm = sred0[0];
#pragma unroll
        for (int w = 1; w < TK_NT / 32; w++) gm = fmaxf(gm, sred0[w]);

        // ---- exp2 + sum ----
        float e[TK_PER];
        float s = 0.f;
#pragma unroll
        for (int j = 0; j < TK_PER; j++) {
            e[j] = exp2f(ws[j] - gm);
            s += e[j];
        }
        float wsum = warpSum(s);
        if (lane == 0) sred1[wid] = wsum;
        __syncthreads();
        float S = sred1[0];
#pragma unroll
        for (int w = 1; w < TK_NT / 32; w++) S += sred1[w];
        const float rs = 1.0f / S;        // S >= 1 always

        // ---- accumulate khot, suppress (per-element fast/slow path) ----
#pragma unroll
        for (int j = 0; j < TK_PER; j++) {
            float p = e[j] * rs;
            kh[j] += p;
            float t;
            if (p > 6.1e-5f) {
                t = __log2f(fmaxf(1.0f - p, 1e-30f)) * 10.0f;      // rare
            } else {
                t = -(p + 0.5f * p * p) * LOG2E10;                 // common
            }
            ws[j] += t;
        }
        __syncthreads();   // protect sred0 for next iteration
    }

    const float* xr = X + (size_t)row * D_DIM;
    bf16* xh = XMhi + (size_t)row * D_DIM;
    bf16* xl = XMlo + (size_t)row * D_DIM;
#pragma unroll
    for (int j = 0; j < TK_PER; j++) {
        int i = tid + j * TK_NT;
        if (i < D_DIM) {
            float v = xr[i] * kh[j];
            bf16 h, l; split2(v, h, l);
            xh[i] = h; xl[i] = l;
        }
    }
}

// ======================= host side ==========================================
#define SYM(p, s) cudaGetSymbolAddress((void**)&p, s)

template<int BM, int BN, int WM, int WN, int EPI>
static inline void launch_gemm(
    const bf16* Ahi, const bf16* Alo, const bf16* Bhi, const bf16* Blo,
    const float* bias, const float* extra,
    float* Cf, bf16* Chi, bf16* Clo, int M, int N, int K)
{
    constexpr int ASTG = BM * 40, BSTG = 32 * (BN + 8);
    constexpr int smem = (6 * ASTG + 6 * BSTG) * 2;
    cudaFuncSetAttribute(gemm_bs<BM, BN, WM, WN, EPI>,
                         cudaFuncAttributeMaxDynamicSharedMemorySize, smem);
    dim3 g((N + BN - 1) / BN, M / BM);
    gemm_bs<BM, BN, WM, WN, EPI><<<g, 256, smem>>>(
        Ahi, Alo, Bhi, Blo, bias, extra, Cf, Chi, Clo, M, N, K);
}

extern "C" void kernel_launch(void* const* d_in, const int* in_sizes, int n_in,
                              void* d_out, int out_size)
{
    const float* x        = (const float*)d_in[0];
    const float* noise_u  = (const float*)d_in[1];
    const float* eps      = (const float*)d_in[2];
    const float* wc_w1    = (const float*)d_in[3];
    const float* wc_b1    = (const float*)d_in[4];
    const float* bn_g     = (const float*)d_in[5];
    const float* bn_b     = (const float*)d_in[6];
    const float* wc_w2    = (const float*)d_in[7];
    const float* wc_b2    = (const float*)d_in[8];
    const float* enc_w1   = (const float*)d_in[9];
    const float* enc_b1   = (const float*)d_in[10];
    const float* enc_w2   = (const float*)d_in[11];
    const float* enc_b2   = (const float*)d_in[12];
    const float* enc_w3   = (const float*)d_in[13];
    const float* enc_b3   = (const float*)d_in[14];
    const float* enc_w4   = (const float*)d_in[15];
    const float* enc_b4   = (const float*)d_in[16];
    const float* mean_w   = (const float*)d_in[17];
    const float* mean_b   = (const float*)d_in[18];
    const float* logvar_w = (const float*)d_in[19];
    const float* logvar_b = (const float*)d_in[20];
    const float* dec_w1   = (const float*)d_in[21];
    const float* dec_b1   = (const float*)d_in[22];
    const float* dec_w2   = (const float*)d_in[23];
    const float* dec_b2   = (const float*)d_in[24];

    float* out    = (float*)d_out;
    float* mu_x   = out;
    float* mu_lat = out + (size_t)B_ROWS * D_DIM;
    float* logvar = mu_lat + (size_t)B_ROWS * Z_DIM;

    bf16 *xhi,*xlo,*w1hi,*w1lo,*w2hi,*w2lo,*ew1hi,*ew1lo,*ew2hi,*ew2lo,
         *ew3hi,*ew3lo,*ew4hi,*ew4lo,*mwhi,*mwlo,*lwhi,*lwlo,
         *dw1hi,*dw1lo,*dw2hi,*dw2lo,
         *hhi,*hlo,*xmhi,*xmlo,*e1hi,*e1lo,*e2hi,*e2lo,*e3hi,*e3lo,
         *e4hi,*e4lo,*zhi,*zlo,*dhi,*dlo;
    float *hf,*wlog,*mean,*rvar;
    SYM(xhi,g_xhi);   SYM(xlo,g_xlo);
    SYM(w1hi,g_w1hi); SYM(w1lo,g_w1lo); SYM(w2hi,g_w2hi); SYM(w2lo,g_w2lo);
    SYM(ew1hi,g_ew1hi); SYM(ew1lo,g_ew1lo); SYM(ew2hi,g_ew2hi); SYM(ew2lo,g_ew2lo);
    SYM(ew3hi,g_ew3hi); SYM(ew3lo,g_ew3lo); SYM(ew4hi,g_ew4hi); SYM(ew4lo,g_ew4lo);
    SYM(mwhi,g_mwhi); SYM(mwlo,g_mwlo); SYM(lwhi,g_lwhi); SYM(lwlo,g_lwlo);
    SYM(dw1hi,g_dw1hi); SYM(dw1lo,g_dw1lo); SYM(dw2hi,g_dw2hi); SYM(dw2lo,g_dw2lo);
    SYM(hf,g_hf); SYM(hhi,g_hhi); SYM(hlo,g_hlo); SYM(wlog,g_wlog);
    SYM(xmhi,g_xmhi); SYM(xmlo,g_xmlo);
    SYM(e1hi,g_e1hi); SYM(e1lo,g_e1lo); SYM(e2hi,g_e2hi); SYM(e2lo,g_e2lo);
    SYM(e3hi,g_e3hi); SYM(e3lo,g_e3lo); SYM(e4hi,g_e4hi); SYM(e4lo,g_e4lo);
    SYM(zhi,g_zhi); SYM(zlo,g_zlo); SYM(dhi,g_dhi); SYM(dlo,g_dlo);
    SYM(mean,g_mean); SYM(rvar,g_rvar);

    // ---- single fused conversion of all fp32 inputs/weights to splits ----
    ConvTable ct;
    auto seg = [&](int k, const float* s, bf16* h, bf16* l, int n) {
        ct.seg[k].s = (const float4*)s;
        ct.seg[k].h = (bf162*)h;
        ct.seg[k].l = (bf162*)l;
        ct.seg[k].n4 = (unsigned)(n / 4);
    };
    seg(0,  x,        xhi,   xlo,   B_ROWS * D_DIM);
    seg(1,  dec_w2,   dw2hi, dw2lo, 2 * H_DIM * D_DIM);
    seg(2,  enc_w1,   ew1hi, ew1lo, D_DIM * 2 * H_DIM);
    seg(3,  wc_w1,    w1hi,  w1lo,  D_DIM * H_DIM);
    seg(4,  wc_w2,    w2hi,  w2lo,  H_DIM * D_DIM);
    seg(5,  enc_w2,   ew2hi, ew2lo, 2 * H_DIM * H_DIM);
    seg(6,  enc_w3,   ew3hi, ew3lo, H_DIM * H_DIM);
    seg(7,  enc_w4,   ew4hi, ew4lo, H_DIM * H_DIM);
    seg(8,  dec_w1,   dw1hi, dw1lo, Z_DIM * 2 * H_DIM);
    seg(9,  mean_w,   mwhi,  mwlo,  H_DIM * Z_DIM);
    seg(10, logvar_w, lwhi,  lwlo,  H_DIM * Z_DIM);
    unsigned total = 0;
    for (int k = 0; k < NSEG; k++) total += ct.seg[k].n4;
    convert_all<<<(total + 255) / 256, 256>>>(ct, total);

    // ---- weight_creator ----
    launch_gemm<128, 128, 2, 4, EPI_F32>(xhi, xlo, w1hi, w1lo, wc_b1, nullptr,
                                         hf, nullptr, nullptr, B_ROWS, H_DIM, D_DIM);
    bn_stats<<<H_DIM, 256>>>(hf, mean, rvar, B_ROWS, H_DIM);
    bn_apply_relu_conv<<<(B_ROWS * H_DIM + 255) / 256, 256>>>(
        hf, mean, rvar, bn_g, bn_b, hhi, hlo, B_ROWS * H_DIM, H_DIM);
    launch_gemm<128, 128, 2, 4, EPI_GUMBEL>(hhi, hlo, w2hi, w2lo, wc_b2, noise_u,
                                            wlog, nullptr, nullptr, B_ROWS, D_DIM, H_DIM);

    // ---- differentiable top-k + mask ----
    topk_mask_kernel<<<B_ROWS, TK_NT>>>(wlog, x, xmhi, xmlo);

    // ---- encoder ----
    launch_gemm<128, 128, 2, 4, EPI_LEAKY>(xmhi, xmlo, ew1hi, ew1lo, enc_b1, nullptr,
                                           nullptr, e1hi, e1lo, B_ROWS, 2 * H_DIM, D_DIM);
    launch_gemm<128, 128, 2, 4, EPI_LEAKY>(e1hi, e1lo, ew2hi, ew2lo, enc_b2, nullptr,
                                           nullptr, e2hi, e2lo, B_ROWS, H_DIM, 2 * H_DIM);
    launch_gemm<128, 128, 2, 4, EPI_LEAKY>(e2hi, e2lo, ew3hi, ew3lo, enc_b3, nullptr,
                                           nullptr, e3hi, e3lo, B_ROWS, H_DIM, H_DIM);
    launch_gemm<128, 128, 2, 4, EPI_LEAKY>(e3hi, e3lo, ew4hi, ew4lo, enc_b4, nullptr,
                                           nullptr, e4hi, e4lo, B_ROWS, H_DIM, H_DIM);
    launch_gemm<64, 64, 2, 4, EPI_F32>(e4hi, e4lo, mwhi, mwlo, mean_b, nullptr,
                                       mu_lat, nullptr, nullptr, B_ROWS, Z_DIM, H_DIM);
    launch_gemm<64, 64, 2, 4, EPI_F32>(e4hi, e4lo, lwhi, lwlo, logvar_b, nullptr,
                                       logvar, nullptr, nullptr, B_ROWS, Z_DIM, H_DIM);

    // ---- reparameterize ----
    reparam_conv<<<(B_ROWS * Z_DIM + 255) / 256, 256>>>(
        mu_lat, logvar, eps, zhi, zlo, B_ROWS * Z_DIM);

    // ---- decoder ----
    launch_gemm<64, 64, 2, 4, EPI_LEAKY>(zhi, zlo, dw1hi, dw1lo, dec_b1, nullptr,
                                         nullptr, dhi, dlo, B_ROWS, 2 * H_DIM, Z_DIM);
    launch_gemm<128, 128, 2, 4, EPI_SIGMOID>(dhi, dlo, dw2hi, dw2lo, dec_b2, nullptr,
                                             mu_x, nullptr, nullptr, B_ROWS, D_DIM, 2 * H_DIM);
}

// round 9
// speedup vs baseline: 1.9372x; 1.3783x over previous
#include <cuda_runtime.h>
#include <cuda_bf16.h>
#include <math.h>
#include <stdint.h>

#define B_ROWS 4096
#define D_DIM  5000
#define H_DIM  512
#define Z_DIM  64
#define TOPK_K 50

typedef __nv_bfloat16  bf16;
typedef __nv_bfloat162 bf162;

// ======================= scratch (static device globals) =====================
__device__ bf16 g_xhi [B_ROWS*D_DIM],     g_xlo [B_ROWS*D_DIM];
__device__ bf16 g_w1hi[D_DIM*H_DIM],      g_w1lo[D_DIM*H_DIM];
__device__ bf16 g_w2hi[H_DIM*D_DIM],      g_w2lo[H_DIM*D_DIM];
__device__ bf16 g_ew1hi[D_DIM*2*H_DIM],   g_ew1lo[D_DIM*2*H_DIM];
__device__ bf16 g_ew2hi[2*H_DIM*H_DIM],   g_ew2lo[2*H_DIM*H_DIM];
__device__ bf16 g_ew3hi[H_DIM*H_DIM],     g_ew3lo[H_DIM*H_DIM];
__device__ bf16 g_ew4hi[H_DIM*H_DIM],     g_ew4lo[H_DIM*H_DIM];
__device__ bf16 g_mwhi[H_DIM*Z_DIM],      g_mwlo[H_DIM*Z_DIM];
__device__ bf16 g_lwhi[H_DIM*Z_DIM],      g_lwlo[H_DIM*Z_DIM];
__device__ bf16 g_dw1hi[Z_DIM*2*H_DIM],   g_dw1lo[Z_DIM*2*H_DIM];
__device__ bf16 g_dw2hi[2*H_DIM*D_DIM],   g_dw2lo[2*H_DIM*D_DIM];
__device__ float g_hf  [B_ROWS*H_DIM];
__device__ bf16  g_hhi [B_ROWS*H_DIM],    g_hlo [B_ROWS*H_DIM];
__device__ float g_wlog[B_ROWS*D_DIM];
__device__ bf16  g_xmhi[B_ROWS*D_DIM],    g_xmlo[B_ROWS*D_DIM];
__device__ bf16  g_e1hi[B_ROWS*2*H_DIM],  g_e1lo[B_ROWS*2*H_DIM];
__device__ bf16  g_e2hi[B_ROWS*H_DIM],    g_e2lo[B_ROWS*H_DIM];
__device__ bf16  g_e3hi[B_ROWS*H_DIM],    g_e3lo[B_ROWS*H_DIM];
__device__ bf16  g_e4hi[B_ROWS*H_DIM],    g_e4lo[B_ROWS*H_DIM];
__device__ bf16  g_zhi [B_ROWS*Z_DIM],    g_zlo [B_ROWS*Z_DIM];
__device__ bf16  g_dhi [B_ROWS*2*H_DIM],  g_dlo [B_ROWS*2*H_DIM];
__device__ float g_mean[H_DIM], g_rvar[H_DIM];

// ======================= PTX helpers ========================================
__device__ __forceinline__ void cp16(uint32_t dst, const void* src, uint32_t sz) {
    asm volatile("cp.async.cg.shared.global [%0], [%1], 16, %2;"
                 :: "r"(dst), "l"(src), "r"(sz));
}
__device__ __forceinline__ void cp_commit() {
    asm volatile("cp.async.commit_group;" ::: "memory");
}
__device__ __forceinline__ void cp_wait1() {
    asm volatile("cp.async.wait_group 1;" ::: "memory");
}
__device__ __forceinline__ void ldsm4(uint32_t* r, uint32_t a) {
    asm volatile("ldmatrix.sync.aligned.m8n8.x4.shared.b16 {%0,%1,%2,%3}, [%4];"
                 : "=r"(r[0]), "=r"(r[1]), "=r"(r[2]), "=r"(r[3]) : "r"(a));
}
__device__ __forceinline__ void ldsm4t(uint32_t* r, uint32_t a) {
    asm volatile("ldmatrix.sync.aligned.m8n8.x4.trans.shared.b16 {%0,%1,%2,%3}, [%4];"
                 : "=r"(r[0]), "=r"(r[1]), "=r"(r[2]), "=r"(r[3]) : "r"(a));
}
__device__ __forceinline__ void mma_bf16(float* c, const uint32_t* a, const uint32_t* b) {
    asm volatile("mma.sync.aligned.m16n8k16.row.col.f32.bf16.bf16.f32 "
                 "{%0,%1,%2,%3}, {%4,%5,%6,%7}, {%8,%9}, {%0,%1,%2,%3};"
                 : "+f"(c[0]), "+f"(c[1]), "+f"(c[2]), "+f"(c[3])
                 : "r"(a[0]), "r"(a[1]), "r"(a[2]), "r"(a[3]), "r"(b[0]), "r"(b[1]));
}
__device__ __forceinline__ void split2(float v, bf16& h, bf16& l) {
    h = __float2bfloat16(v);
    l = __float2bfloat16(v - __bfloat162float(h));
}

#define EPI_F32     0
#define EPI_LEAKY   1
#define EPI_GUMBEL  2
#define EPI_SIGMOID 3

// ======================= bf16-split tensor-core GEMM ========================
template<int BM, int BN, int WARPS_M, int WARPS_N, int EPI>
__global__ __launch_bounds__(256) void gemm_bs(
    const bf16* __restrict__ Ahi, const bf16* __restrict__ Alo,
    const bf16* __restrict__ Bhi, const bf16* __restrict__ Blo,
    const float* __restrict__ bias, const float* __restrict__ extra,
    float* __restrict__ Cf, bf16* __restrict__ Chi, bf16* __restrict__ Clo,
    int M, int N, int K)
{
    static_assert(WARPS_M * WARPS_N == 8, "");
    constexpr int BK   = 32;
    constexpr int AST  = BK + 8;
    constexpr int BNp  = BN + 8;
    constexpr int WTM  = BM / WARPS_M;
    constexpr int WTN  = BN / WARPS_N;
    constexpr int MT   = WTM / 16;
    constexpr int NT   = WTN / 8;
    constexpr int NL   = WTN / 16;
    constexpr int ASTG = BM * AST;
    constexpr int BSTG = BK * BNp;
    constexpr int A_PASS = BM / 64;
    constexpr int B_PASS = BN / 64;

    extern __shared__ bf16 sm[];
    const uint32_t smbase = (uint32_t)__cvta_generic_to_shared(sm);
    const uint32_t offAlo = 3 * ASTG, offBhi = 6 * ASTG, offBlo = 6 * ASTG + 3 * BSTG;

    const int tid  = threadIdx.x;
    const int lane = tid & 31, wid = tid >> 5;
    const int warp_m = wid % WARPS_M, warp_n = wid / WARPS_M;
    const int row0 = blockIdx.y * BM;
    const int col0 = blockIdx.x * BN;
    const int n_iters = (K + BK - 1) / BK;

    auto load_stage = [&](int s) {
        const int buf = s % 3;
        const int k0  = s * BK;
#pragma unroll
        for (int p = 0; p < A_PASS; p++) {
            int vec = tid + p * 256;
            int r = vec >> 2, q = vec & 3;
            size_t so = (size_t)(row0 + r) * K + k0 + q * 8;
            uint32_t ok = (k0 + q * 8 < K) ? 16u : 0u;
            const void* sh = ok ? (const void*)(Ahi + so) : (const void*)Ahi;
            const void* sl = ok ? (const void*)(Alo + so) : (const void*)Alo;
            uint32_t d = (uint32_t)((buf * ASTG + r * AST + q * 8) * 2);
            cp16(smbase + d, sh, ok);
            cp16(smbase + offAlo * 2 + d, sl, ok);
        }
#pragma unroll
        for (int p = 0; p < B_PASS; p++) {
            int vec = tid + p * 256;
            int kr = vec / (BN / 8), q = vec % (BN / 8);
            size_t so = (size_t)(k0 + kr) * N + col0 + q * 8;
            uint32_t ok = ((k0 + kr < K) && (col0 + q * 8 < N)) ? 16u : 0u;
            const void* sh = ok ? (const void*)(Bhi + so) : (const void*)Bhi;
            const void* sl = ok ? (const void*)(Blo + so) : (const void*)Blo;
            uint32_t d = (uint32_t)((buf * BSTG + kr * BNp + q * 8) * 2);
            cp16(smbase + offBhi * 2 + d, sh, ok);
            cp16(smbase + offBlo * 2 + d, sl, ok);
        }
    };

    load_stage(0); cp_commit();
    if (1 < n_iters) load_stage(1);
    cp_commit();

    float acc[MT][NT][4];
#pragma unroll
    for (int i = 0; i < MT; i++)
#pragma unroll
        for (int j = 0; j < NT; j++)
#pragma unroll
            for (int q = 0; q < 4; q++) acc[i][j][q] = 0.f;

    const int lrow  = lane & 15;
    const int lhalf = (lane >> 4) << 3;

    for (int it = 0; it < n_iters; it++) {
        cp_wait1();
        __syncthreads();
        const int buf = it % 3;

#pragma unroll
        for (int kk = 0; kk < BK; kk += 16) {
            uint32_t afh[MT][4], afl[MT][4], bfh[NT][2], bfl[NT][2];
#pragma unroll
            for (int i = 0; i < MT; i++) {
                int r = warp_m * WTM + i * 16 + lrow;
                uint32_t a = smbase + (uint32_t)((buf * ASTG + r * AST + kk + lhalf) * 2);
                ldsm4(afh[i], a);
                ldsm4(afl[i], a + offAlo * 2);
            }
#pragma unroll
            for (int j = 0; j < NL; j++) {
                int kr = kk + (lane & 15);
                int cc = warp_n * WTN + j * 16 + lhalf;
                uint32_t a = smbase + offBhi * 2
                           + (uint32_t)((buf * BSTG + kr * BNp + cc) * 2);
                ldsm4t(&bfh[2 * j][0], a);
                ldsm4t(&bfl[2 * j][0], a + (offBlo - offBhi) * 2);
            }
#pragma unroll
            for (int i = 0; i < MT; i++)
#pragma unroll
                for (int j = 0; j < NT; j++) mma_bf16(acc[i][j], afh[i], bfh[j]);
#pragma unroll
            for (int i = 0; i < MT; i++)
#pragma unroll
                for (int j = 0; j < NT; j++) mma_bf16(acc[i][j], afh[i], bfl[j]);
#pragma unroll
            for (int i = 0; i < MT; i++)
#pragma unroll
                for (int j = 0; j < NT; j++) mma_bf16(acc[i][j], afl[i], bfh[j]);
        }

        int s = it + 2;
        if (s < n_iters) load_stage(s);
        cp_commit();
        __syncthreads();
    }

#pragma unroll
    for (int i = 0; i < MT; i++) {
#pragma unroll
        for (int j = 0; j < NT; j++) {
            int row = row0 + warp_m * WTM + i * 16 + (lane >> 2);
            int col = col0 + warp_n * WTN + j * 8 + (lane & 3) * 2;
            if (col >= N) continue;
            float b0 = bias[col], b1 = bias[col + 1];
#pragma unroll
            for (int h = 0; h < 2; h++) {
                int r = row + h * 8;
                float v0 = acc[i][j][2 * h + 0] + b0;
                float v1 = acc[i][j][2 * h + 1] + b1;
                size_t off = (size_t)r * N + col;
                if (EPI == EPI_F32) {
                    *reinterpret_cast<float2*>(&Cf[off]) = make_float2(v0, v1);
                } else if (EPI == EPI_LEAKY) {
                    v0 = (v0 > 0.f) ? v0 : 0.01f * v0;
                    v1 = (v1 > 0.f) ? v1 : 0.01f * v1;
                    bf16 h0, l0, h1, l1;
                    split2(v0, h0, l0); split2(v1, h1, l1);
                    *reinterpret_cast<bf162*>(&Chi[off]) = __halves2bfloat162(h0, h1);
                    *reinterpret_cast<bf162*>(&Clo[off]) = __halves2bfloat162(l0, l1);
                } else if (EPI == EPI_GUMBEL) {
                    float2 u = *reinterpret_cast<const float2*>(&extra[off]);
                    v0 += __logf(-__logf(u.x + 1e-30f));
                    v1 += __logf(-__logf(u.y + 1e-30f));
                    *reinterpret_cast<float2*>(&Cf[off]) = make_float2(v0, v1);
                } else {
                    v0 = 1.0f / (1.0f + __expf(-v0));
                    v1 = 1.0f / (1.0f + __expf(-v1));
                    *reinterpret_cast<float2*>(&Cf[off]) = make_float2(v0, v1);
                }
            }
        }
    }
}

// ======================= fused segmented split-convert ======================
#define NSEG 11
struct ConvSeg { const float4* s; bf162* h; bf162* l; unsigned n4; };
struct ConvTable { ConvSeg seg[NSEG]; };

__global__ __launch_bounds__(256) void convert_all(ConvTable t, unsigned total)
{
    unsigned idx = blockIdx.x * 256 + threadIdx.x;
    if (idx >= total) return;
#pragma unroll
    for (int k = 0; k < NSEG; k++) {
        if (idx < t.seg[k].n4) {
            float4 v = t.seg[k].s[idx];
            bf16 h0, l0, h1, l1, h2, l2, h3, l3;
            split2(v.x, h0, l0); split2(v.y, h1, l1);
            split2(v.z, h2, l2); split2(v.w, h3, l3);
            t.seg[k].h[2 * idx]     = __halves2bfloat162(h0, h1);
            t.seg[k].h[2 * idx + 1] = __halves2bfloat162(h2, h3);
            t.seg[k].l[2 * idx]     = __halves2bfloat162(l0, l1);
            t.seg[k].l[2 * idx + 1] = __halves2bfloat162(l2, l3);
            return;
        }
        idx -= t.seg[k].n4;
    }
}

// ======================= BN / reparam =======================================
__global__ __launch_bounds__(256) void bn_stats(
    const float* __restrict__ h, float* __restrict__ mean, float* __restrict__ rvar,
    int M, int N)
{
    const int c = blockIdx.x;
    float s = 0.f, s2 = 0.f;
    for (int r = threadIdx.x; r < M; r += 256) {
        float v = h[(size_t)r * N + c];
        s += v; s2 += v * v;
    }
    __shared__ float sh[256], sh2[256];
    sh[threadIdx.x] = s; sh2[threadIdx.x] = s2;
    __syncthreads();
    for (int o = 128; o > 0; o >>= 1) {
        if (threadIdx.x < o) {
            sh[threadIdx.x]  += sh[threadIdx.x + o];
            sh2[threadIdx.x] += sh2[threadIdx.x + o];
        }
        __syncthreads();
    }
    if (threadIdx.x == 0) {
        float m = sh[0] / (float)M;
        float var = sh2[0] / (float)M - m * m;
        mean[c] = m;
        rvar[c] = rsqrtf(var + 1e-5f);
    }
}

__global__ __launch_bounds__(256) void bn_apply_relu_conv(
    const float* __restrict__ h, const float* __restrict__ mean,
    const float* __restrict__ rvar, const float* __restrict__ g,
    const float* __restrict__ b, bf16* __restrict__ hi, bf16* __restrict__ lo,
    int total, int N)
{
    int i = blockIdx.x * 256 + threadIdx.x;
    if (i >= total) return;
    int c = i % N;
    float v = (h[i] - mean[c]) * rvar[c] * g[c] + b[c];
    v = v > 0.f ? v : 0.f;
    bf16 hh, ll; split2(v, hh, ll);
    hi[i] = hh; lo[i] = ll;
}

__global__ __launch_bounds__(256) void reparam_conv(
    const float* __restrict__ mu, const float* __restrict__ logvar,
    const float* __restrict__ eps, bf16* __restrict__ zhi, bf16* __restrict__ zlo,
    int total)
{
    int i = blockIdx.x * 256 + threadIdx.x;
    if (i >= total) return;
    float z = mu[i] + eps[i] * __expf(0.5f * logvar[i]);
    bf16 h, l; split2(z, h, l);
    zhi[i] = h; zlo[i] = l;
}

// ======================= continuous top-k: active-set version ===============
// Reference recurrence per iteration (T=0.1):
//   p = softmax(w/T);  khot += p;  w += log(max(1-p, 1e-30))
// In e-space with e = exp((w - M0)/T):
//   p = e/S;  e *= max(1-p,1e-30)^(1/T) = mask^10     <-- the ^10 is critical
// Winners get mask~1e-30 -> e underflows to 0 (matches reference underflow
// after max-subtraction).  Active set = elements within ~4 units of M0
// (count-calibrated >=1280 via histogram); excluded elements have p < e^-40
// at all times -> kh < 1e-17, and their S contribution < 1e-14 relative.
#define TK_NT   256
#define TK_PER  20
#define TK_CAP  2048
#define TK_TGT  1280
#define LOG2E10 14.426950408889634f

__global__ __launch_bounds__(TK_NT) void topk_mask_kernel(
    const float* __restrict__ W, const float* __restrict__ X,
    bf16* __restrict__ XMhi, bf16* __restrict__ XMlo)
{
    __shared__ float s_selw[TK_CAP];
    __shared__ int   s_seli[TK_CAP];
    __shared__ int   s_hist[256];
    __shared__ int   s_scan[TK_NT];
    __shared__ float s_redA[TK_NT / 32];
    __shared__ float s_sum[2][TK_NT / 32];
    __shared__ float s_tau;
    __shared__ int   s_na;

    const int row  = blockIdx.x;
    const int tid  = threadIdx.x;
    const int lane = tid & 31;
    const int wid  = tid >> 5;
    const float* wr = W + (size_t)row * D_DIM;

    // ---- pass 1: load w, block max ----
    float wv[TK_PER];
#pragma unroll
    for (int j = 0; j < TK_PER; j++) {
        int i = tid + j * TK_NT;
        wv[j] = (i < D_DIM) ? wr[i] : -INFINITY;
    }
    float m = wv[0];
#pragma unroll
    for (int j = 1; j < TK_PER; j++) m = fmaxf(m, wv[j]);
#pragma unroll
    for (int o = 16; o; o >>= 1) m = fmaxf(m, __shfl_xor_sync(0xffffffffu, m, o));
    if (lane == 0) s_redA[wid] = m;
    if (tid < 256) s_hist[tid] = 0;
    __syncthreads();
    float M0 = s_redA[0];
#pragma unroll
    for (int w = 1; w < TK_NT / 32; w++) M0 = fmaxf(M0, s_redA[w]);

    // ---- pass 2: histogram of (M0 - w), bin width 0.125, 256 bins ----
#pragma unroll
    for (int j = 0; j < TK_PER; j++) {
        int i = tid + j * TK_NT;
        if (i < D_DIM) {
            int b = (int)((M0 - wv[j]) * 8.0f);
            b = b < 0 ? 0 : (b > 255 ? 255 : b);
            atomicAdd(&s_hist[b], 1);
        }
    }
    __syncthreads();
    if (tid == 0) {
        int cum = 0, B = 255, prev = 0;
        for (int b = 0; b < 256; b++) {
            prev = cum;
            cum += s_hist[b];
            if (cum >= TK_TGT) {
                B = (cum > TK_CAP && b > 0 && prev >= 1) ? b - 1 : b;
                break;
            }
        }
        s_tau = M0 - (float)(B + 1) * 0.125f;   // select w > tau (bin <= B)
    }
    __syncthreads();
    const float tau = s_tau;

    // ---- pass 3: deterministic compaction (per-thread count + block scan) --
    int cnt = 0;
#pragma unroll
    for (int j = 0; j < TK_PER; j++) {
        int i = tid + j * TK_NT;
        if (i < D_DIM && wv[j] > tau) cnt++;
    }
    s_scan[tid] = cnt;
    __syncthreads();
    for (int off = 1; off < TK_NT; off <<= 1) {
        int v = (tid >= off) ? s_scan[tid - off] : 0;
        __syncthreads();
        s_scan[tid] += v;
        __syncthreads();
    }
    int pos = s_scan[tid] - cnt;             // exclusive prefix
    if (tid == TK_NT - 1) s_na = (s_scan[TK_NT - 1] < TK_CAP) ? s_scan[TK_NT - 1] : TK_CAP;
#pragma unroll
    for (int j = 0; j < TK_PER; j++) {
        int i = tid + j * TK_NT;
        if (i < D_DIM && wv[j] > tau) {
            if (pos < TK_CAP) { s_selw[pos] = wv[j]; s_seli[pos] = i; }
            pos++;
        }
    }
    __syncthreads();
    const int NA = s_na;

    // ---- iterate on compacted active set (registers, 8 slots/thread) ------
    constexpr int SL = TK_CAP / TK_NT;        // 8
    float e[SL], kh[SL];
#pragma unroll
    for (int k = 0; k < SL; k++) {
        int s = tid + k * TK_NT;
        e[k]  = (s < NA) ? exp2f((s_selw[s] - M0) * LOG2E10) : 0.f;
        kh[k] = 0.f;
    }

    int par = 0;
    for (int it = 0; it < TOPK_K; it++) {
        float s = e[0];
#pragma unroll
        for (int k = 1; k < SL; k++) s += e[k];
#pragma unroll
        for (int o = 16; o; o >>= 1) s += __shfl_xor_sync(0xffffffffu, s, o);
        if (lane == 0) s_sum[par][wid] = s;
        __syncthreads();
        float S = s_sum[par][0];
#pragma unroll
        for (int w = 1; w < TK_NT / 32; w++) S += s_sum[par][w];
        const float rs = 1.0f / S;
#pragma unroll
        for (int k = 0; k < SL; k++) {
            float p = e[k] * rs;
            kh[k] += p;
            float m1 = fmaxf(1.0f - p, 1e-30f);
            float m2 = m1 * m1;
            float m4 = m2 * m2;
            float m8 = m4 * m4;
            e[k] *= m8 * m2;                   // mask^10 == mask^(1/T)
        }
        par ^= 1;                              // parity buffer: 1 barrier/iter
    }

    // ---- write xm: zero row, then scatter selected x*kh --------------------
    bf162* xh2 = (bf162*)(XMhi + (size_t)row * D_DIM);
    bf162* xl2 = (bf162*)(XMlo + (size_t)row * D_DIM);
    const bf162 z2 = __halves2bfloat162(__float2bfloat16(0.f), __float2bfloat16(0.f));
    for (int i = tid; i < D_DIM / 2; i += TK_NT) { xh2[i] = z2; xl2[i] = z2; }
    __syncthreads();
    const float* xr = X + (size_t)row * D_DIM;
    bf16* xh = XMhi + (size_t)row * D_DIM;
    bf16* xl = XMlo + (size_t)row * D_DIM;
#pragma unroll
    for (int k = 0; k < SL; k++) {
        int s = tid + k * TK_NT;
        if (s < NA) {
            int i = s_seli[s];
            float v = xr[i] * kh[k];
            bf16 h, l; split2(v, h, l);
            xh[i] = h; xl[i] = l;
        }
    }
}

// ======================= host side ==========================================
#define SYM(p, s) cudaGetSymbolAddress((void**)&p, s)

template<int BM, int BN, int WM, int WN, int EPI>
static inline void launch_gemm(
    const bf16* Ahi, const bf16* Alo, const bf16* Bhi, const bf16* Blo,
    const float* bias, const float* extra,
    float* Cf, bf16* Chi, bf16* Clo, int M, int N, int K)
{
    constexpr int ASTG = BM * 40, BSTG = 32 * (BN + 8);
    constexpr int smem = (6 * ASTG + 6 * BSTG) * 2;
    cudaFuncSetAttribute(gemm_bs<BM, BN, WM, WN, EPI>,
                         cudaFuncAttributeMaxDynamicSharedMemorySize, smem);
    dim3 g((N + BN - 1) / BN, M / BM);
    gemm_bs<BM, BN, WM, WN, EPI><<<g, 256, smem>>>(
        Ahi, Alo, Bhi, Blo, bias, extra, Cf, Chi, Clo, M, N, K);
}

extern "C" void kernel_launch(void* const* d_in, const int* in_sizes, int n_in,
                              void* d_out, int out_size)
{
    const float* x        = (const float*)d_in[0];
    const float* noise_u  = (const float*)d_in[1];
    const float* eps      = (const float*)d_in[2];
    const float* wc_w1    = (const float*)d_in[3];
    const float* wc_b1    = (const float*)d_in[4];
    const float* bn_g     = (const float*)d_in[5];
    const float* bn_b     = (const float*)d_in[6];
    const float* wc_w2    = (const float*)d_in[7];
    const float* wc_b2    = (const float*)d_in[8];
    const float* enc_w1   = (const float*)d_in[9];
    const float* enc_b1   = (const float*)d_in[10];
    const float* enc_w2   = (const float*)d_in[11];
    const float* enc_b2   = (const float*)d_in[12];
    const float* enc_w3   = (const float*)d_in[13];
    const float* enc_b3   = (const float*)d_in[14];
    const float* enc_w4   = (const float*)d_in[15];
    const float* enc_b4   = (const float*)d_in[16];
    const float* mean_w   = (const float*)d_in[17];
    const float* mean_b   = (const float*)d_in[18];
    const float* logvar_w = (const float*)d_in[19];
    const float* logvar_b = (const float*)d_in[20];
    const float* dec_w1   = (const float*)d_in[21];
    const float* dec_b1   = (const float*)d_in[22];
    const float* dec_w2   = (const float*)d_in[23];
    const float* dec_b2   = (const float*)d_in[24];

    float* out    = (float*)d_out;
    float* mu_x   = out;
    float* mu_lat = out + (size_t)B_ROWS * D_DIM;
    float* logvar = mu_lat + (size_t)B_ROWS * Z_DIM;

    bf16 *xhi,*xlo,*w1hi,*w1lo,*w2hi,*w2lo,*ew1hi,*ew1lo,*ew2hi,*ew2lo,
         *ew3hi,*ew3lo,*ew4hi,*ew4lo,*mwhi,*mwlo,*lwhi,*lwlo,
         *dw1hi,*dw1lo,*dw2hi,*dw2lo,
         *hhi,*hlo,*xmhi,*xmlo,*e1hi,*e1lo,*e2hi,*e2lo,*e3hi,*e3lo,
         *e4hi,*e4lo,*zhi,*zlo,*dhi,*dlo;
    float *hf,*wlog,*mean,*rvar;
    SYM(xhi,g_xhi);   SYM(xlo,g_xlo);
    SYM(w1hi,g_w1hi); SYM(w1lo,g_w1lo); SYM(w2hi,g_w2hi); SYM(w2lo,g_w2lo);
    SYM(ew1hi,g_ew1hi); SYM(ew1lo,g_ew1lo); SYM(ew2hi,g_ew2hi); SYM(ew2lo,g_ew2lo);
    SYM(ew3hi,g_ew3hi); SYM(ew3lo,g_ew3lo); SYM(ew4hi,g_ew4hi); SYM(ew4lo,g_ew4lo);
    SYM(mwhi,g_mwhi); SYM(mwlo,g_mwlo); SYM(lwhi,g_lwhi); SYM(lwlo,g_lwlo);
    SYM(dw1hi,g_dw1hi); SYM(dw1lo,g_dw1lo); SYM(dw2hi,g_dw2hi); SYM(dw2lo,g_dw2lo);
    SYM(hf,g_hf); SYM(hhi,g_hhi); SYM(hlo,g_hlo); SYM(wlog,g_wlog);
    SYM(xmhi,g_xmhi); SYM(xmlo,g_xmlo);
    SYM(e1hi,g_e1hi); SYM(e1lo,g_e1lo); SYM(e2hi,g_e2hi); SYM(e2lo,g_e2lo);
    SYM(e3hi,g_e3hi); SYM(e3lo,g_e3lo); SYM(e4hi,g_e4hi); SYM(e4lo,g_e4lo);
    SYM(zhi,g_zhi); SYM(zlo,g_zlo); SYM(dhi,g_dhi); SYM(dlo,g_dlo);
    SYM(mean,g_mean); SYM(rvar,g_rvar);

    // ---- single fused conversion of all fp32 inputs/weights to splits ----
    ConvTable ct;
    auto seg = [&](int k, const float* s, bf16* h, bf16* l, int n) {
        ct.seg[k].s = (const float4*)s;
        ct.seg[k].h = (bf162*)h;
        ct.seg[k].l = (bf162*)l;
        ct.seg[k].n4 = (unsigned)(n / 4);
    };
    seg(0,  x,        xhi,   xlo,   B_ROWS * D_DIM);
    seg(1,  dec_w2,   dw2hi, dw2lo, 2 * H_DIM * D_DIM);
    seg(2,  enc_w1,   ew1hi, ew1lo, D_DIM * 2 * H_DIM);
    seg(3,  wc_w1,    w1hi,  w1lo,  D_DIM * H_DIM);
    seg(4,  wc_w2,    w2hi,  w2lo,  H_DIM * D_DIM);
    seg(5,  enc_w2,   ew2hi, ew2lo, 2 * H_DIM * H_DIM);
    seg(6,  enc_w3,   ew3hi, ew3lo, H_DIM * H_DIM);
    seg(7,  enc_w4,   ew4hi, ew4lo, H_DIM * H_DIM);
    seg(8,  dec_w1,   dw1hi, dw1lo, Z_DIM * 2 * H_DIM);
    seg(9,  mean_w,   mwhi,  mwlo,  H_DIM * Z_DIM);
    seg(10, logvar_w, lwhi,  lwlo,  H_DIM * Z_DIM);
    unsigned total = 0;
    for (int k = 0; k < NSEG; k++) total += ct.seg[k].n4;
    convert_all<<<(total + 255) / 256, 256>>>(ct, total);

    // ---- weight_creator ----
    launch_gemm<128, 128, 2, 4, EPI_F32>(xhi, xlo, w1hi, w1lo, wc_b1, nullptr,
                                         hf, nullptr, nullptr, B_ROWS, H_DIM, D_DIM);
    bn_stats<<<H_DIM, 256>>>(hf, mean, rvar, B_ROWS, H_DIM);
    bn_apply_relu_conv<<<(B_ROWS * H_DIM + 255) / 256, 256>>>(
        hf, mean, rvar, bn_g, bn_b, hhi, hlo, B_ROWS * H_DIM, H_DIM);
    launch_gemm<128, 128, 2, 4, EPI_GUMBEL>(hhi, hlo, w2hi, w2lo, wc_b2, noise_u,
                                            wlog, nullptr, nullptr, B_ROWS, D_DIM, H_DIM);

    // ---- differentiable top-k + mask (active-set) ----
    topk_mask_kernel<<<B_ROWS, TK_NT>>>(wlog, x, xmhi, xmlo);

    // ---- encoder ----
    launch_gemm<128, 128, 2, 4, EPI_LEAKY>(xmhi, xmlo, ew1hi, ew1lo, enc_b1, nullptr,
                                           nullptr, e1hi, e1lo, B_ROWS, 2 * H_DIM, D_DIM);
    launch_gemm<128, 128, 2, 4, EPI_LEAKY>(e1hi, e1lo, ew2hi, ew2lo, enc_b2, nullptr,
                                           nullptr, e2hi, e2lo, B_ROWS, H_DIM, 2 * H_DIM);
    launch_gemm<128, 128, 2, 4, EPI_LEAKY>(e2hi, e2lo, ew3hi, ew3lo, enc_b3, nullptr,
                                           nullptr, e3hi, e3lo, B_ROWS, H_DIM, H_DIM);
    launch_gemm<128, 128, 2, 4, EPI_LEAKY>(e3hi, e3lo, ew4hi, ew4lo, enc_b4, nullptr,
                                           nullptr, e4hi, e4lo, B_ROWS, H_DIM, H_DIM);
    launch_gemm<64, 64, 2, 4, EPI_F32>(e4hi, e4lo, mwhi, mwlo, mean_b, nullptr,
                                       mu_lat, nullptr, nullptr, B_ROWS, Z_DIM, H_DIM);
    launch_gemm<64, 64, 2, 4, EPI_F32>(e4hi, e4lo, lwhi, lwlo, logvar_b, nullptr,
                                       logvar, nullptr, nullptr, B_ROWS, Z_DIM, H_DIM);

    // ---- reparameterize ----
    reparam_conv<<<(B_ROWS * Z_DIM + 255) / 256, 256>>>(
        mu_lat, logvar, eps, zhi, zlo, B_ROWS * Z_DIM);

    // ---- decoder ----
    launch_gemm<64, 64, 2, 4, EPI_LEAKY>(zhi, zlo, dw1hi, dw1lo, dec_b1, nullptr,
                                         nullptr, dhi, dlo, B_ROWS, 2 * H_DIM, Z_DIM);
    launch_gemm<128, 128, 2, 4, EPI_SIGMOID>(dhi, dlo, dw2hi, dw2lo, dec_b2, nullptr,
                                             mu_x, nullptr, nullptr, B_ROWS, D_DIM, 2 * H_DIM);
}